// round 3
// baseline (speedup 1.0000x reference)
#include <cuda_runtime.h>

using ull = unsigned long long;
#define DEV __device__ __forceinline__

constexpr int Bn   = 65536;   // batch
constexpr int Hh   = 64;      // hidden
constexpr int Gg   = 192;     // 3*H
constexpr int Kf   = 1024;    // T*H
constexpr int Ktot = 1088;    // + H (cWhh/c section)

// scratch (device globals — no allocations allowed)
__device__ float g_hidden[(size_t)Bn * Hh];        // per-row GRU output for its own type
__device__ float g_cWt[(size_t)Ktot * Gg];         // k-major [k][g]: cWih (k<1024) then cWhh

DEV float sigm(float v) { return 1.0f / (1.0f + __expf(-v)); }

DEV ull pk(float lo, float hi) {
    ull r; asm("mov.b64 %0, {%1, %2};" : "=l"(r) : "f"(lo), "f"(hi)); return r;
}
DEV float2 upk(ull v) {
    float2 r; asm("mov.b64 {%0, %1}, %2;" : "=f"(r.x), "=f"(r.y) : "l"(v)); return r;
}
DEV ull f2fma(ull a, ull b, ull c) {
    ull d; asm("fma.rn.f32x2 %0, %1, %2, %3;" : "=l"(d) : "l"(a), "l"(b), "l"(c)); return d;
}

// ---------------------------------------------------------------------------
// Build k-major core weight matrix: g_cWt[k*192+g] = (k<1024) ? cWih[g][k] : cWhh[g][k-1024]
// ---------------------------------------------------------------------------
__global__ void buildW_kernel(const float* __restrict__ cWih, const float* __restrict__ cWhh) {
    int idx = blockIdx.x * 256 + threadIdx.x;
    if (idx >= Ktot * Gg) return;
    int k = idx / Gg, g = idx - k * Gg;
    g_cWt[idx] = (k < Kf) ? cWih[(size_t)g * Kf + k] : cWhh[g * Hh + (k - Kf)];
}

// ---------------------------------------------------------------------------
// Stage A: per-(type, chunk) block. Compact matching rows, run the per-type
// GRU (gi = Wih@x + bih, gh = Whh@reg + bhh) → g_hidden.
// ---------------------------------------------------------------------------
constexpr int SMEMA_FLOATS = 64 * Gg * 2 + 2048 * 2 + 1024 + 8;
constexpr int SMEMA_BYTES  = SMEMA_FLOATS * 4;   // 118816

__global__ void __launch_bounds__(256, 1)
stageA_kernel(const float* __restrict__ x, const int* __restrict__ typ,
              const float* __restrict__ regs,
              const float* __restrict__ Wih, const float* __restrict__ Whh,
              const float* __restrict__ bih, const float* __restrict__ bhh)
{
    extern __shared__ float sm[];
    float* WI = sm;                    // [64][192] k-major
    float* WH = WI + 64 * Gg;          // [64][192]
    float* xs = WH + 64 * Gg;          // 8 warps * 4 rows * 64
    float* rs = xs + 2048;
    int*  list = (int*)(rs + 2048);    // up to 1024 indices
    int*  pcnt = list + 1024;

    const int tid = threadIdx.x;
    const int t   = blockIdx.y;
    const int c0  = blockIdx.x * 1024;

    if (tid == 0) *pcnt = 0;
    __syncthreads();
    for (int i = tid; i < 1024; i += 256) {
        if (typ[c0 + i] == t) list[atomicAdd(pcnt, 1)] = c0 + i;
    }
    __syncthreads();
    const int n = *pcnt;
    if (n == 0) return;

    // load + transpose weights (thread g handles one g-row; stores conflict-free)
    if (tid < Gg) {
        const float* wi = Wih + ((size_t)t * Gg + tid) * 64;
        const float* wh = Whh + ((size_t)t * Gg + tid) * 64;
        #pragma unroll
        for (int q = 0; q < 16; q++) {
            float4 a = *(const float4*)(wi + q * 4);
            WI[(q*4+0)*Gg + tid] = a.x; WI[(q*4+1)*Gg + tid] = a.y;
            WI[(q*4+2)*Gg + tid] = a.z; WI[(q*4+3)*Gg + tid] = a.w;
            float4 b = *(const float4*)(wh + q * 4);
            WH[(q*4+0)*Gg + tid] = b.x; WH[(q*4+1)*Gg + tid] = b.y;
            WH[(q*4+2)*Gg + tid] = b.z; WH[(q*4+3)*Gg + tid] = b.w;
        }
    }
    __syncthreads();

    const int w = tid >> 5, l = tid & 31;
    const float* bip = bih + t * Gg + 2 * l;
    const float* bhp = bhh + t * Gg + 2 * l;
    const float2 bI0 = *(const float2*)(bip),      bI1 = *(const float2*)(bip + 64),
                 bI2 = *(const float2*)(bip + 128);
    const float2 bH0 = *(const float2*)(bhp),      bH1 = *(const float2*)(bhp + 64),
                 bH2 = *(const float2*)(bhp + 128);
    float* xw = xs + w * 256;   // this warp's 4 staged x rows
    float* rw = rs + w * 256;   // this warp's 4 staged register rows

    for (int base = w * 4; base < n; base += 32) {
        int bi4[4];
        #pragma unroll
        for (int i = 0; i < 4; i++) {
            int j = base + i; if (j > n - 1) j = n - 1;
            bi4[i] = list[j];
        }
        #pragma unroll
        for (int i = 0; i < 4; i++) {
            *(float2*)(xw + i * 64 + 2 * l) = *(const float2*)(x    + (size_t)bi4[i] * 64 + 2 * l);
            *(float2*)(rw + i * 64 + 2 * l) = *(const float2*)(regs + (size_t)bi4[i] * Kf + t * 64 + 2 * l);
        }
        __syncwarp();

        float2 gi0[4], gi1[4], gi2[4], gh0[4], gh1[4], gh2[4];
        #pragma unroll
        for (int i = 0; i < 4; i++) {
            gi0[i] = bI0; gi1[i] = bI1; gi2[i] = bI2;
            gh0[i] = bH0; gh1[i] = bH1; gh2[i] = bH2;
        }

        #pragma unroll 4
        for (int k = 0; k < 64; k++) {
            const float* wk = WI + k * Gg + 2 * l;
            float2 wi0 = *(const float2*)(wk),       wi1 = *(const float2*)(wk + 64),
                   wi2 = *(const float2*)(wk + 128);
            const float* hk = WH + k * Gg + 2 * l;
            float2 wh0 = *(const float2*)(hk),       wh1 = *(const float2*)(hk + 64),
                   wh2 = *(const float2*)(hk + 128);
            #pragma unroll
            for (int i = 0; i < 4; i++) {
                float xv = xw[i * 64 + k];
                float rv = rw[i * 64 + k];
                gi0[i].x = fmaf(wi0.x, xv, gi0[i].x); gi0[i].y = fmaf(wi0.y, xv, gi0[i].y);
                gi1[i].x = fmaf(wi1.x, xv, gi1[i].x); gi1[i].y = fmaf(wi1.y, xv, gi1[i].y);
                gi2[i].x = fmaf(wi2.x, xv, gi2[i].x); gi2[i].y = fmaf(wi2.y, xv, gi2[i].y);
                gh0[i].x = fmaf(wh0.x, rv, gh0[i].x); gh0[i].y = fmaf(wh0.y, rv, gh0[i].y);
                gh1[i].x = fmaf(wh1.x, rv, gh1[i].x); gh1[i].y = fmaf(wh1.y, rv, gh1[i].y);
                gh2[i].x = fmaf(wh2.x, rv, gh2[i].x); gh2[i].y = fmaf(wh2.y, rv, gh2[i].y);
            }
        }

        #pragma unroll
        for (int i = 0; i < 4; i++) {
            if (base + i < n) {
                float2 hv = *(const float2*)(rw + i * 64 + 2 * l);
                float r0 = sigm(gi0[i].x + gh0[i].x);
                float z0 = sigm(gi1[i].x + gh1[i].x);
                float n0 = tanhf(gi2[i].x + r0 * gh2[i].x);
                float o0 = (1.0f - z0) * n0 + z0 * hv.x;
                float r1 = sigm(gi0[i].y + gh0[i].y);
                float z1 = sigm(gi1[i].y + gh1[i].y);
                float n1 = tanhf(gi2[i].y + r1 * gh2[i].y);
                float o1 = (1.0f - z1) * n1 + z1 * hv.y;
                *(float2*)(g_hidden + (size_t)bi4[i] * 64 + 2 * l) = make_float2(o0, o1);
            }
        }
        __syncwarp();
    }
}

// ---------------------------------------------------------------------------
// Stage B: GEMM M=65536, N=192, K=1088 with in-loader register substitution
// and fused GRU epilogue. f32x2 packed along M (row pairs).
// Block: 64 rows x 192 cols, 256 threads = (tm 16) x (tn 16), thread tile 4m x 12n.
// ---------------------------------------------------------------------------
constexpr int APAD = 68;   // 64 + 4 pad; 272B row stride keeps 16B alignment

template<bool TAIL>
DEV void mmaTile(const float* As, const float* Ws, int tm, int tn,
                 ull (&acc)[3][4][2], ull (&acch)[4][2])
{
    #pragma unroll 4
    for (int k = 0; k < 16; k++) {
        float4 a0 = *(const float4*)&As[k * APAD + tm * 4];
        ull ap0 = pk(a0.x, a0.y);
        ull ap1 = pk(a0.z, a0.w);
        const float* wp = &Ws[k * Gg + tn * 4];
        #pragma unroll
        for (int g = 0; g < 3; g++) {
            float4 wv = *(const float4*)(wp + g * 64);
            ull b0 = pk(wv.x, wv.x), b1 = pk(wv.y, wv.y);
            ull b2 = pk(wv.z, wv.z), b3 = pk(wv.w, wv.w);
            if (!TAIL || g < 2) {
                acc[g][0][0] = f2fma(ap0, b0, acc[g][0][0]); acc[g][0][1] = f2fma(ap1, b0, acc[g][0][1]);
                acc[g][1][0] = f2fma(ap0, b1, acc[g][1][0]); acc[g][1][1] = f2fma(ap1, b1, acc[g][1][1]);
                acc[g][2][0] = f2fma(ap0, b2, acc[g][2][0]); acc[g][2][1] = f2fma(ap1, b2, acc[g][2][1]);
                acc[g][3][0] = f2fma(ap0, b3, acc[g][3][0]); acc[g][3][1] = f2fma(ap1, b3, acc[g][3][1]);
            } else {
                acch[0][0] = f2fma(ap0, b0, acch[0][0]); acch[0][1] = f2fma(ap1, b0, acch[0][1]);
                acch[1][0] = f2fma(ap0, b1, acch[1][0]); acch[1][1] = f2fma(ap1, b1, acch[1][1]);
                acch[2][0] = f2fma(ap0, b2, acch[2][0]); acch[2][1] = f2fma(ap1, b2, acch[2][1]);
                acch[3][0] = f2fma(ap0, b3, acch[3][0]); acch[3][1] = f2fma(ap1, b3, acch[3][1]);
            }
        }
    }
}

__global__ void __launch_bounds__(256, 2)
stageB_kernel(const float* __restrict__ regs, const int* __restrict__ typ,
              const float* __restrict__ c,
              const float* __restrict__ cbih, const float* __restrict__ cbhh,
              float* __restrict__ out)
{
    __shared__ __align__(16) float As[16 * APAD];
    __shared__ __align__(16) float Ws[16 * Gg];
    __shared__ int styp[64];

    const int tid = threadIdx.x;
    const int bm  = blockIdx.x * 64;
    const int tm  = tid & 15, tn = tid >> 4;
    const int lrow = tid >> 2, lq = tid & 3;

    if (tid < 64) styp[tid] = typ[bm + tid];
    __syncthreads();

    ull acc[3][4][2];
    ull acch[4][2];
    #pragma unroll
    for (int g = 0; g < 3; g++)
        #pragma unroll
        for (int q = 0; q < 4; q++) { acc[g][q][0] = 0ull; acc[g][q][1] = 0ull; }
    #pragma unroll
    for (int q = 0; q < 4; q++) { acch[q][0] = 0ull; acch[q][1] = 0ull; }

    for (int kt = 0; kt < Ktot / 16; kt++) {
        const int k0 = kt * 16;
        // ---- load A tile (with register-update substitution / c tail) ----
        {
            const int b = bm + lrow;
            const float* src;
            if (k0 < Kf) {
                src = ((k0 >> 6) == styp[lrow])
                        ? (g_hidden + (size_t)b * 64 + (k0 & 63))
                        : (regs     + (size_t)b * Kf + k0);
            } else {
                src = c + (size_t)b * 64 + (k0 - Kf);
            }
            float4 v = *(const float4*)(src + lq * 4);
            As[(lq*4+0)*APAD + lrow] = v.x;
            As[(lq*4+1)*APAD + lrow] = v.y;
            As[(lq*4+2)*APAD + lrow] = v.z;
            As[(lq*4+3)*APAD + lrow] = v.w;
        }
        // ---- load W tile (k-major, contiguous) ----
        {
            const float* src = g_cWt + (size_t)k0 * Gg;
            #pragma unroll
            for (int i = 0; i < 3; i++) {
                int idx = (tid + i * 256) * 4;
                *(float4*)&Ws[idx] = *(const float4*)(src + idx);
            }
        }
        __syncthreads();
        if (k0 < Kf) mmaTile<false>(As, Ws, tm, tn, acc, acch);
        else         mmaTile<true >(As, Ws, tm, tn, acc, acch);
        __syncthreads();
    }

    // ---- fused GRU epilogue ----
    float bR[4], bZ[4], bN[4], bHN[4];
    #pragma unroll
    for (int q = 0; q < 4; q++) {
        int h = tn * 4 + q;
        bR[q]  = cbih[h]       + cbhh[h];
        bZ[q]  = cbih[64 + h]  + cbhh[64 + h];
        bN[q]  = cbih[128 + h];
        bHN[q] = cbhh[128 + h];
    }
    #pragma unroll
    for (int p = 0; p < 2; p++) {
        const int m0 = tm * 4 + 2 * p;
        const int b0 = bm + m0, b1 = b0 + 1;
        float4 cv0 = *(const float4*)(c + (size_t)b0 * 64 + tn * 4);
        float4 cv1 = *(const float4*)(c + (size_t)b1 * 64 + tn * 4);
        float cc0[4] = {cv0.x, cv0.y, cv0.z, cv0.w};
        float cc1[4] = {cv1.x, cv1.y, cv1.z, cv1.w};
        float o0[4], o1[4];
        #pragma unroll
        for (int q = 0; q < 4; q++) {
            float2 ar = upk(acc[0][q][p]);
            float2 az = upk(acc[1][q][p]);
            float2 an = upk(acc[2][q][p]);
            float2 ah = upk(acch[q][p]);
            float r0 = sigm(ar.x + bR[q]);
            float z0 = sigm(az.x + bZ[q]);
            float n0 = tanhf(an.x + bN[q] + r0 * (ah.x + bHN[q]));
            o0[q] = (1.0f - z0) * n0 + z0 * cc0[q];
            float r1 = sigm(ar.y + bR[q]);
            float z1 = sigm(az.y + bZ[q]);
            float n1 = tanhf(an.y + bN[q] + r1 * (ah.y + bHN[q]));
            o1[q] = (1.0f - z1) * n1 + z1 * cc1[q];
        }
        *(float4*)(out + (size_t)b0 * 64 + tn * 4) = make_float4(o0[0], o0[1], o0[2], o0[3]);
        *(float4*)(out + (size_t)b1 * 64 + tn * 4) = make_float4(o1[0], o1[1], o1[2], o1[3]);
    }
}

// ---------------------------------------------------------------------------
extern "C" void kernel_launch(void* const* d_in, const int* in_sizes, int n_in,
                              void* d_out, int out_size)
{
    const float* x    = (const float*)d_in[0];
    const int*   typ  = (const int*)  d_in[1];
    const float* c    = (const float*)d_in[2];
    const float* regs = (const float*)d_in[3];
    const float* Wih  = (const float*)d_in[4];
    const float* Whh  = (const float*)d_in[5];
    const float* bih  = (const float*)d_in[6];
    const float* bhh  = (const float*)d_in[7];
    const float* cWih = (const float*)d_in[8];
    const float* cWhh = (const float*)d_in[9];
    const float* cbih = (const float*)d_in[10];
    const float* cbhh = (const float*)d_in[11];
    float* out = (float*)d_out;

    (void)in_sizes; (void)n_in; (void)out_size;

    cudaFuncSetAttribute(stageA_kernel,
                         cudaFuncAttributeMaxDynamicSharedMemorySize, SMEMA_BYTES);

    buildW_kernel<<<(Ktot * Gg + 255) / 256, 256>>>(cWih, cWhh);
    stageA_kernel<<<dim3(64, 16), 256, SMEMA_BYTES>>>(x, typ, regs, Wih, Whh, bih, bhh);
    stageB_kernel<<<Bn / 64, 256>>>(regs, typ, c, cbih, cbhh, out);
}